// round 4
// baseline (speedup 1.0000x reference)
#include <cuda_runtime.h>
#include <math.h>

#define BB 64
#define TT 512
#define DIN 64
#define HH 512
#define G4 2048
#define DOUT 32

// ---------------- scratch (__device__ globals; no runtime allocation) --------
__device__ __align__(256) float g_xg[BB * TT * G4];   // gate pre-activations
__device__ __align__(256) float g_h1[BB * TT * HH];   // layer-0 output sequence
__device__ __align__(256) float g_gh[2][BB * HH];     // ping-pong hidden state
__device__ __align__(256) float g_hlast[BB * HH];     // layer-1 final h
__device__ unsigned g_bar;

typedef unsigned long long u64;

// ---------------- f32x2 helpers (Blackwell packed fp32 pipe) ------------------
__device__ __forceinline__ void fma2(u64& d, u64 a, u64 b) {
    asm("fma.rn.f32x2 %0, %1, %2, %0;" : "+l"(d) : "l"(a), "l"(b));
}
__device__ __forceinline__ float2 upk2(u64 v) {
    float lo, hi;
    asm("mov.b64 {%0, %1}, %2;" : "=f"(lo), "=f"(hi) : "l"(v));
    return make_float2(lo, hi);
}
__device__ __forceinline__ float sigm(float x) { return 1.0f / (1.0f + expf(-x)); }

// ---------------- C[M][N] = A[M][K] * B[N][K]^T + b1[n] + b2[n] ---------------
// BM=BN=64, BK=16, 256 threads, 4x4 thread tile, f32x2 dual-lane accumulation.
__global__ void __launch_bounds__(256) gemm_abT(
    float* __restrict__ C, const float* __restrict__ A, const float* __restrict__ Bm,
    const float* __restrict__ bias1, const float* __restrict__ bias2,
    int M, int N, int K)
{
    __shared__ __align__(16) float As[8 * 136];  // [k_pair][m*2 + parity]
    __shared__ __align__(16) float Bs[8 * 136];

    int tid = threadIdx.x;
    int bm = blockIdx.y, bn = blockIdx.x;
    int tx = tid & 15, ty = tid >> 4;

    u64 acc[4][4];
#pragma unroll
    for (int i = 0; i < 4; i++)
#pragma unroll
        for (int j = 0; j < 4; j++) acc[i][j] = 0ull;

    int r  = tid >> 2;         // 0..63 row within tile
    int kq = (tid & 3) * 4;    // 0,4,8,12
    const float* Ag = A + (size_t)(bm * 64 + r) * K + kq;
    const float* Bg = Bm + (size_t)(bn * 64 + r) * K + kq;

    for (int kt = 0; kt < K; kt += 16) {
        float4 av = *(const float4*)(Ag + kt);
        float4 bv = *(const float4*)(Bg + kt);
        __syncthreads();
        int s0 = (kq >> 1) * 136 + r * 2;
        *(float2*)(As + s0)       = make_float2(av.x, av.y);
        *(float2*)(As + s0 + 136) = make_float2(av.z, av.w);
        *(float2*)(Bs + s0)       = make_float2(bv.x, bv.y);
        *(float2*)(Bs + s0 + 136) = make_float2(bv.z, bv.w);
        __syncthreads();
#pragma unroll
        for (int kk = 0; kk < 8; kk++) {
            const ulonglong2* ap = (const ulonglong2*)(As + kk * 136 + ty * 8);
            const ulonglong2* bp = (const ulonglong2*)(Bs + kk * 136 + tx * 8);
            ulonglong2 a01 = ap[0], a23 = ap[1];
            ulonglong2 b01 = bp[0], b23 = bp[1];
            u64 af[4] = {a01.x, a01.y, a23.x, a23.y};
            u64 bf[4] = {b01.x, b01.y, b23.x, b23.y};
#pragma unroll
            for (int i = 0; i < 4; i++)
#pragma unroll
                for (int j = 0; j < 4; j++) fma2(acc[i][j], af[i], bf[j]);
        }
    }

#pragma unroll
    for (int i = 0; i < 4; i++) {
        int row = bm * 64 + ty * 4 + i;
        float4 o;
        float* ov = &o.x;
#pragma unroll
        for (int j = 0; j < 4; j++) {
            int coln = bn * 64 + tx * 4 + j;
            float2 s = upk2(acc[i][j]);
            ov[j] = s.x + s.y + bias1[coln] + bias2[coln];
        }
        *(float4*)(C + (size_t)row * N + bn * 64 + tx * 4) = o;
    }
}

// ---------------- persistent LSTM recurrence ---------------------------------
// grid = 128 co-resident CTAs, 256 threads. CTA owns h cols [4c,4c+4).
// thread: b = tid&63, jj = tid>>6; computes all 4 gates for (b, col).
#define SM_H  (64 * 514)      // staged h, row stride 514 (odd u64 stride)
#define SM_W  (16 * 520)      // 16 W_hh rows, stride 520 (16B-aligned)
#define SMEM_REC_BYTES ((SM_H + SM_W) * 4)

__global__ void __launch_bounds__(256, 1) lstm_rec(
    const float* __restrict__ Whh,   // [2048,512]
    const float* __restrict__ xg,    // [B,T,2048] = x-proj + b_ih + b_hh
    float* __restrict__ hseq,        // [B,T,512] or nullptr
    float* __restrict__ hlast)       // [B,512]   or nullptr
{
    extern __shared__ float sm[];
    float* h_s = sm;
    float* w_s = sm + SM_H;

    int tid = threadIdx.x;
    int b   = tid & 63;
    int jj  = tid >> 6;
    int col = blockIdx.x * 4 + jj;

    for (int i = tid; i < 16 * 512; i += 256) {
        int row = i >> 9, k = i & 511;
        int g = row >> 2, j2 = row & 3;
        w_s[row * 520 + k] = Whh[(size_t)(g * 512 + blockIdx.x * 4 + j2) * 512 + k];
    }
    float c = 0.0f;
    __syncthreads();

    const float* w0 = w_s + (0 * 4 + jj) * 520;
    const float* w1 = w_s + (1 * 4 + jj) * 520;
    const float* w2 = w_s + (2 * 4 + jj) * 520;
    const float* w3 = w_s + (3 * 4 + jj) * 520;

    for (int t = 0; t < TT; t++) {
        const float* xp = xg + ((size_t)(b * TT + t) << 11) + col;
        float xv0 = __ldcs(xp);
        float xv1 = __ldcs(xp + 512);
        float xv2 = __ldcs(xp + 1024);
        float xv3 = __ldcs(xp + 1536);

        // stage h_prev from L2 (L1 is stale across SMs)
        const float2* ghp = (const float2*)(g_gh[t & 1]);
        for (int v = tid; v < (BB * HH / 2); v += 256) {
            float2 hv = __ldcg(ghp + v);
            int bb = v >> 8;
            int k2 = v & 255;
            *(float2*)(h_s + bb * 514 + k2 * 2) = hv;
        }
        __syncthreads();

        u64 a0 = 0, a1 = 0, a2 = 0, a3 = 0;
        const u64* hb = (const u64*)(h_s + b * 514);
#pragma unroll 16
        for (int kk = 0; kk < 512; kk += 4) {
            u64 h01 = hb[kk >> 1];
            u64 h23 = hb[(kk >> 1) + 1];
            ulonglong2 wv0 = *(const ulonglong2*)(w0 + kk);
            ulonglong2 wv1 = *(const ulonglong2*)(w1 + kk);
            ulonglong2 wv2 = *(const ulonglong2*)(w2 + kk);
            ulonglong2 wv3 = *(const ulonglong2*)(w3 + kk);
            fma2(a0, h01, wv0.x); fma2(a0, h23, wv0.y);
            fma2(a1, h01, wv1.x); fma2(a1, h23, wv1.y);
            fma2(a2, h01, wv2.x); fma2(a2, h23, wv2.y);
            fma2(a3, h01, wv3.x); fma2(a3, h23, wv3.y);
        }
        float2 s0 = upk2(a0), s1 = upk2(a1), s2 = upk2(a2), s3 = upk2(a3);
        float gi = s0.x + s0.y + xv0;
        float gf = s1.x + s1.y + xv1;
        float gg = s2.x + s2.y + xv2;
        float go = s3.x + s3.y + xv3;

        c = sigm(gf) * c + sigm(gi) * tanhf(gg);
        float h = sigm(go) * tanhf(c);

        __stcg(g_gh[(t + 1) & 1] + b * HH + col, h);
        if (hseq)  hseq[((size_t)(b * TT + t) << 9) + col] = h;
        if (hlast && t == TT - 1) hlast[b * HH + col] = h;

        __threadfence();
        __syncthreads();
        if (tid == 0) {
            atomicAdd(&g_bar, 1u);
            unsigned target = gridDim.x * (unsigned)(t + 1);
            volatile unsigned* vb = &g_bar;
            while (*vb < target) { }
        }
        __syncthreads();
    }
}

// ---------------- init: zero ping-pong h and barrier --------------------------
__global__ void init_state() {
    int i = blockIdx.x * blockDim.x + threadIdx.x;
    if (i == 0) g_bar = 0u;
    if (i < 2 * BB * HH) ((float*)g_gh)[i] = 0.0f;
}

// ---------------- final projection [64,512] x [32,512]^T + b ------------------
__global__ void out_gemm(float* __restrict__ out, const float* __restrict__ hl,
                         const float* __restrict__ Wo, const float* __restrict__ bo)
{
    int i = blockIdx.x * blockDim.x + threadIdx.x;
    if (i >= BB * DOUT) return;
    int b = i >> 5, n = i & 31;
    const float4* hp = (const float4*)(hl + b * HH);
    const float4* wp = (const float4*)(Wo + n * HH);
    float s = 0.0f;
#pragma unroll 8
    for (int k = 0; k < HH / 4; k++) {
        float4 hv = hp[k], wv = wp[k];
        s += hv.x * wv.x + hv.y * wv.y + hv.z * wv.z + hv.w * wv.w;
    }
    out[i] = s + bo[n];
}

// ---------------- launch ------------------------------------------------------
extern "C" void kernel_launch(void* const* d_in, const int* in_sizes, int n_in,
                              void* d_out, int out_size)
{
    const float* x    = (const float*)d_in[0];
    const float* Wih0 = (const float*)d_in[1];
    const float* Whh0 = (const float*)d_in[2];
    const float* bih0 = (const float*)d_in[3];
    const float* bhh0 = (const float*)d_in[4];
    const float* Wih1 = (const float*)d_in[5];
    const float* Whh1 = (const float*)d_in[6];
    const float* bih1 = (const float*)d_in[7];
    const float* bhh1 = (const float*)d_in[8];
    const float* Wout = (const float*)d_in[9];
    const float* bout = (const float*)d_in[10];
    float* out = (float*)d_out;

    cudaFuncSetAttribute(lstm_rec, cudaFuncAttributeMaxDynamicSharedMemorySize,
                         SMEM_REC_BYTES);

    void *pxg, *ph1, *phl;
    cudaGetSymbolAddress(&pxg, g_xg);
    cudaGetSymbolAddress(&ph1, g_h1);
    cudaGetSymbolAddress(&phl, g_hlast);
    float* xg = (float*)pxg;
    float* h1 = (float*)ph1;
    float* hl = (float*)phl;

    dim3 ggrid(G4 / 64, (BB * TT) / 64);

    // layer 0
    init_state<<<256, 256>>>();
    gemm_abT<<<ggrid, 256>>>(xg, x, Wih0, bih0, bhh0, BB * TT, G4, DIN);
    lstm_rec<<<128, 256, SMEM_REC_BYTES>>>(Whh0, xg, h1, nullptr);

    // layer 1
    init_state<<<256, 256>>>();
    gemm_abT<<<ggrid, 256>>>(xg, h1, Wih1, bih1, bhh1, BB * TT, G4, HH);
    lstm_rec<<<128, 256, SMEM_REC_BYTES>>>(Whh1, xg, nullptr, hl);

    // output projection
    out_gemm<<<(BB * DOUT + 127) / 128, 128>>>(out, hl, Wout, bout);
}

// round 9
// speedup vs baseline: 1.1575x; 1.1575x over previous
#include <cuda_runtime.h>
#include <cuda_bf16.h>
#include <math.h>
#include <stdint.h>

#define BB 64
#define TT 512
#define HH 512
#define G4 2048
#define DOUT 32

typedef unsigned long long u64;

__device__ __align__(256) float g_xg[BB*TT*G4];
__device__ __align__(256) float g_h1[BB*TT*HH];
__device__ __align__(256) __nv_bfloat16 g_hA[2][128*HH];  // rows 0-63 hi, 64-127 lo
__device__ __align__(256) float g_hlast[BB*HH];
__device__ unsigned g_bar;

// smem byte offsets (recurrence kernel)
#define SA    0                      // A: 128 rows x 1024B (swizzled)
#define SWHI  131072                 // Whi: 32 rows x 1024B (swizzled)
#define SWLO  163840
#define SD0   196608                 // D partial (k-low): 64x36 floats
#define SD1   205824
#define SXB   215040                 // xg buf: 64x36 floats
#define SMEM_REC 224256

__device__ __forceinline__ float sigm(float x){ return 1.0f/(1.0f+expf(-x)); }
__device__ __forceinline__ void fma2(u64& d,u64 a,u64 b){ asm("fma.rn.f32x2 %0, %1, %2, %0;":"+l"(d):"l"(a),"l"(b)); }
__device__ __forceinline__ float2 upk2(u64 v){ float lo,hi; asm("mov.b64 {%0, %1}, %2;":"=f"(lo),"=f"(hi):"l"(v)); return make_float2(lo,hi); }
__device__ __forceinline__ void mma16816(float* d, const uint32_t* a, const uint32_t* b){
    asm volatile("mma.sync.aligned.m16n8k16.row.col.f32.bf16.bf16.f32 "
        "{%0,%1,%2,%3}, {%4,%5,%6,%7}, {%8,%9}, {%0,%1,%2,%3};"
        : "+f"(d[0]),"+f"(d[1]),"+f"(d[2]),"+f"(d[3])
        : "r"(a[0]),"r"(a[1]),"r"(a[2]),"r"(a[3]),"r"(b[0]),"r"(b[1]));
}
__device__ __forceinline__ void bar_rel(unsigned* p){ asm volatile("red.release.gpu.global.add.u32 [%0], 1;"::"l"(p):"memory"); }
__device__ __forceinline__ unsigned bar_acq(unsigned* p){ unsigned v; asm volatile("ld.acquire.gpu.global.u32 %0, [%1];":"=r"(v):"l"(p):"memory"); return v; }

// ---------- xg GEMM (f32x2, validated): C = A*B^T + b1 + b2 ----------
__global__ void __launch_bounds__(256) gemm_abT(float* __restrict__ C, const float* __restrict__ A,
    const float* __restrict__ Bm, const float* __restrict__ b1, const float* __restrict__ b2,
    int M, int N, int K)
{
    __shared__ __align__(16) float As[8*136], Bs[8*136];
    int tid=threadIdx.x, bm=blockIdx.y, bn=blockIdx.x, tx=tid&15, ty=tid>>4;
    u64 acc[4][4];
#pragma unroll
    for(int i=0;i<4;i++)
#pragma unroll
        for(int j=0;j<4;j++) acc[i][j]=0ull;
    int r=tid>>2, kq=(tid&3)*4;
    const float* Ag=A+(size_t)(bm*64+r)*K+kq;
    const float* Bg=Bm+(size_t)(bn*64+r)*K+kq;
    for(int kt=0;kt<K;kt+=16){
        float4 av=*(const float4*)(Ag+kt), bv=*(const float4*)(Bg+kt);
        __syncthreads();
        int s0=(kq>>1)*136+r*2;
        *(float2*)(As+s0)=make_float2(av.x,av.y); *(float2*)(As+s0+136)=make_float2(av.z,av.w);
        *(float2*)(Bs+s0)=make_float2(bv.x,bv.y); *(float2*)(Bs+s0+136)=make_float2(bv.z,bv.w);
        __syncthreads();
#pragma unroll
        for(int kk=0;kk<8;kk++){
            const ulonglong2* ap=(const ulonglong2*)(As+kk*136+ty*8);
            const ulonglong2* bp=(const ulonglong2*)(Bs+kk*136+tx*8);
            ulonglong2 a01=ap[0],a23=ap[1],b01=bp[0],b23=bp[1];
            u64 af[4]={a01.x,a01.y,a23.x,a23.y}, bf[4]={b01.x,b01.y,b23.x,b23.y};
#pragma unroll
            for(int i=0;i<4;i++)
#pragma unroll
                for(int j=0;j<4;j++) fma2(acc[i][j],af[i],bf[j]);
        }
    }
#pragma unroll
    for(int i=0;i<4;i++){
        int row=bm*64+ty*4+i; float4 o; float* ov=&o.x;
#pragma unroll
        for(int j=0;j<4;j++){ int cn=bn*64+tx*4+j; float2 s=upk2(acc[i][j]); ov[j]=s.x+s.y+b1[cn]+b2[cn]; }
        *(float4*)(C+(size_t)row*N+bn*64+tx*4)=o;
    }
}

// ---------- persistent mma.sync LSTM recurrence ----------
// 64 CTAs x 256 thr. CTA owns hidden cols [8c,8c+8) -> 32 gate-rows (n = 4*j+g).
// Per step: D[64,32] = Ahi*Whi + Ahi*Wlo + Alo*Whi  (K'=1536, bf16 hi/lo split).
// Warps 0-3 compute m32n32 tiles, k-split 2; epilogue on all 256 threads.
__global__ void __launch_bounds__(256,1) lstm_rec_mma(
    const float* __restrict__ Whh, const float* __restrict__ xg,
    float* __restrict__ hseq, float* __restrict__ hlast)
{
    extern __shared__ char sm[];
    int tid=threadIdx.x, wid=tid>>5, lane=tid&31;
    int gid=lane>>2, tig=lane&3;
    int col0=blockIdx.x*8;

    // stage W hi/lo -> [n][k] rows 1024B, 16B-chunk XOR swizzle by n&7
    for(int e=tid;e<32*512;e+=256){
        int n=e>>9, k=e&511;
        float w=Whh[(size_t)((n&3)*HH + col0 + (n>>2))*HH + k];
        __nv_bfloat16 hi=__float2bfloat16(w);
        __nv_bfloat16 lo=__float2bfloat16(w-__bfloat162float(hi));
        int kb=k*2;
        int off=n*1024 + ((((kb>>4)^(n&7)))<<4) + (kb&15);
        *(__nv_bfloat16*)(sm+SWHI+off)=hi;
        *(__nv_bfloat16*)(sm+SWLO+off)=lo;
    }
    int eb=tid>>2, ejp=tid&3;     // epilogue cell owner: batch eb, cols ejp*2, +1
    float c0=0.f, c1=0.f;
    __syncthreads();

    for(int t=0;t<TT;t++){
        // stage A = [hhi;hlo] 128x512 bf16 from L2, swizzled
        const uint4* src=(const uint4*)g_hA[t&1];
#pragma unroll 4
        for(int it=0;it<32;it++){
            int idx=tid+it*256;
            int r=idx>>6, kc=idx&63;
            uint4 v=__ldcg(src+idx);
            *(uint4*)(sm+SA+r*1024+((kc^(r&7))<<4))=v;
        }
        // stage xg -> xbuf[b][4j+g] (pad 36)
        {
            int b=tid>>2, g=tid&3;
            const float4* q=(const float4*)(xg+((size_t)(b*TT+t)<<11)+g*512+col0);
            float4 v0=__ldcs(q), v1=__ldcs(q+1);
            float* xb=(float*)(sm+SXB)+b*36+g;
            xb[0]=v0.x; xb[4]=v0.y; xb[8]=v0.z; xb[12]=v0.w;
            xb[16]=v1.x; xb[20]=v1.y; xb[24]=v1.z; xb[28]=v1.w;
        }
        __syncthreads();

        if(wid<4){
            int wm=(wid&1)*32;
            int k0=(wid>>1)*48;
            float d[8][4];
#pragma unroll
            for(int i=0;i<8;i++){ d[i][0]=0.f; d[i][1]=0.f; d[i][2]=0.f; d[i][3]=0.f; }
            int ra[4], rw[4];
#pragma unroll
            for(int i=0;i<4;i++){ ra[i]=(wm+i*8+gid)*1024; rw[i]=(i*8+gid)*1024; }
            for(int ki=0;ki<48;ki++){
                int kk=k0+ki;                         // 0..95 over K'=1536
                const char* ab=sm+SA+((kk>=64)?65536:0);           // Ahi / Alo rows
                const char* wb=sm+((kk>=32&&kk<64)?SWLO:SWHI);     // Whi,Wlo,Whi
                int ck=(kk&31)*2;                     // 16B-chunk index of k16 block
                int o0=((ck^gid)<<4)+tig*4;
                int o1=(((ck+1)^gid)<<4)+tig*4;
                uint32_t a[2][4], bf[4][2];
#pragma unroll
                for(int mf=0;mf<2;mf++){
                    a[mf][0]=*(const uint32_t*)(ab+ra[mf*2]+o0);
                    a[mf][1]=*(const uint32_t*)(ab+ra[mf*2+1]+o0);
                    a[mf][2]=*(const uint32_t*)(ab+ra[mf*2]+o1);
                    a[mf][3]=*(const uint32_t*)(ab+ra[mf*2+1]+o1);
                }
#pragma unroll
                for(int nf=0;nf<4;nf++){
                    bf[nf][0]=*(const uint32_t*)(wb+rw[nf]+o0);
                    bf[nf][1]=*(const uint32_t*)(wb+rw[nf]+o1);
                }
#pragma unroll
                for(int mf=0;mf<2;mf++)
#pragma unroll
                    for(int nf=0;nf<4;nf++)
                        mma16816(d[mf*4+nf], a[mf], bf[nf]);
            }
            float* db=(float*)(sm+((wid>>1)?SD1:SD0));
#pragma unroll
            for(int mf=0;mf<2;mf++)
#pragma unroll
                for(int nf=0;nf<4;nf++){
                    int r=wm+mf*16+gid, n=nf*8+tig*2;
                    float* p=db+r*36+n;   p[0]=d[mf*4+nf][0]; p[1]=d[mf*4+nf][1];
                    float* p2=db+(r+8)*36+n; p2[0]=d[mf*4+nf][2]; p2[1]=d[mf*4+nf][3];
                }
        }
        __syncthreads();

        // epilogue: thread owns cells (eb, ejp*2) and (eb, ejp*2+1)
        {
            const float* d0=(const float*)(sm+SD0)+eb*36;
            const float* d1=(const float*)(sm+SD1)+eb*36;
            const float* xb=(const float*)(sm+SXB)+eb*36;
            float hv[2];
#pragma unroll
            for(int cc=0;cc<2;cc++){
                int j=ejp*2+cc;
                float4 p=*(const float4*)(d0+4*j);
                float4 q=*(const float4*)(d1+4*j);
                float4 xv=*(const float4*)(xb+4*j);
                float gi=p.x+q.x+xv.x, gf=p.y+q.y+xv.y;
                float gg=p.z+q.z+xv.z, go=p.w+q.w+xv.w;
                float& c = cc ? c1 : c0;
                c = sigm(gf)*c + sigm(gi)*tanhf(gg);
                hv[cc] = sigm(go)*tanhf(c);
            }
            __nv_bfloat16 h0=__float2bfloat16(hv[0]), h1=__float2bfloat16(hv[1]);
            __nv_bfloat16 l0=__float2bfloat16(hv[0]-__bfloat162float(h0));
            __nv_bfloat16 l1=__float2bfloat16(hv[1]-__bfloat162float(h1));
            uint32_t hp=(uint32_t)__bfloat16_as_ushort(h0)|((uint32_t)__bfloat16_as_ushort(h1)<<16);
            uint32_t lp=(uint32_t)__bfloat16_as_ushort(l0)|((uint32_t)__bfloat16_as_ushort(l1)<<16);
            __nv_bfloat16* dst=g_hA[(t+1)&1];
            int cbase=col0+ejp*2;
            *(uint32_t*)(dst+(size_t)eb*HH+cbase)=hp;
            *(uint32_t*)(dst+(size_t)(64+eb)*HH+cbase)=lp;
            if(hseq) *(float2*)(hseq+((size_t)eb*TT+t)*HH+cbase)=make_float2(hv[0],hv[1]);
            if(hlast && t==TT-1) *(float2*)(hlast+(size_t)eb*HH+cbase)=make_float2(hv[0],hv[1]);
        }

        // grid barrier
        __threadfence();
        __syncthreads();
        if(tid==0){
            bar_rel(&g_bar);
            unsigned target=(unsigned)gridDim.x*(unsigned)(t+1);
            while(bar_acq(&g_bar)<target){}
        }
        __syncthreads();
    }
}

__global__ void init_state(){
    int i=blockIdx.x*blockDim.x+threadIdx.x;
    if(i==0) g_bar=0u;
    if(i<2*128*HH/2) ((uint32_t*)g_hA)[i]=0u;
}

__global__ void out_gemm(float* __restrict__ out, const float* __restrict__ hl,
                         const float* __restrict__ Wo, const float* __restrict__ bo)
{
    int i=blockIdx.x*blockDim.x+threadIdx.x;
    if(i>=BB*DOUT) return;
    int b=i>>5, n=i&31;
    const float4* hp=(const float4*)(hl+b*HH);
    const float4* wp=(const float4*)(Wo+n*HH);
    float s=0.0f;
#pragma unroll 8
    for(int k=0;k<HH/4;k++){ float4 hv=hp[k],wv=wp[k]; s+=hv.x*wv.x+hv.y*wv.y+hv.z*wv.z+hv.w*wv.w; }
    out[i]=s+bo[n];
}

extern "C" void kernel_launch(void* const* d_in, const int* in_sizes, int n_in,
                              void* d_out, int out_size)
{
    const float* x   =(const float*)d_in[0];
    const float* Wih0=(const float*)d_in[1];
    const float* Whh0=(const float*)d_in[2];
    const float* bih0=(const float*)d_in[3];
    const float* bhh0=(const float*)d_in[4];
    const float* Wih1=(const float*)d_in[5];
    const float* Whh1=(const float*)d_in[6];
    const float* bih1=(const float*)d_in[7];
    const float* bhh1=(const float*)d_in[8];
    const float* Wout=(const float*)d_in[9];
    const float* bout=(const float*)d_in[10];
    float* out=(float*)d_out;

    cudaFuncSetAttribute(lstm_rec_mma, cudaFuncAttributeMaxDynamicSharedMemorySize, SMEM_REC);

    void *pxg,*ph1,*phl;
    cudaGetSymbolAddress(&pxg,g_xg);
    cudaGetSymbolAddress(&ph1,g_h1);
    cudaGetSymbolAddress(&phl,g_hlast);
    float* xg=(float*)pxg; float* h1=(float*)ph1; float* hl=(float*)phl;

    dim3 gg(G4/64,(BB*TT)/64);

    init_state<<<256,256>>>();
    gemm_abT<<<gg,256>>>(xg,x,Wih0,bih0,bhh0,BB*TT,G4,64);
    lstm_rec_mma<<<64,256,SMEM_REC>>>(Whh0,xg,h1,nullptr);

    init_state<<<256,256>>>();
    gemm_abT<<<gg,256>>>(xg,h1,Wih1,bih1,bhh1,BB*TT,G4,HH);
    lstm_rec_mma<<<64,256,SMEM_REC>>>(Whh1,xg,nullptr,hl);

    out_gemm<<<(BB*DOUT+127)/128,128>>>(out,hl,Wout,bout);
}

// round 13
// speedup vs baseline: 1.2749x; 1.1015x over previous
#include <cuda_runtime.h>
#include <cuda_bf16.h>
#include <math.h>
#include <stdint.h>

#define BB 64
#define TT 512
#define HH 512
#define G4 2048
#define DOUT 32

typedef unsigned long long u64;

__device__ __align__(256) float g_xg[BB*TT*G4];
__device__ __align__(256) float g_h1[BB*TT*HH];
__device__ __align__(256) __nv_bfloat16 g_hA[2][128*HH];  // rows 0-63 hi, 64-127 lo
__device__ __align__(256) float g_hlast[BB*HH];
__device__ unsigned g_bar;

// smem byte offsets (recurrence kernel)
#define SA    0                      // A: 128 rows x 1024B (swizzled)
#define SWHI  131072                 // Whi: 32 rows x 1024B
#define SWLO  163840
#define SD0   196608                 // 4 D partial bufs, [m=batch64][n=gate32+2] f32
#define DSTR  34
#define DBUF  (64*DSTR*4)            // 8704 B per buf
#define SMEM_REC (SD0 + 4*DBUF)     // 231424

__device__ __forceinline__ float rcpa(float x){ float y; asm("rcp.approx.f32 %0, %1;":"=f"(y):"f"(x)); return y; }
__device__ __forceinline__ float sigm(float x){ return rcpa(1.0f+__expf(-x)); }
__device__ __forceinline__ float tanh_f(float x){ return 2.0f*rcpa(1.0f+__expf(-2.0f*x))-1.0f; }
__device__ __forceinline__ void fma2(u64& d,u64 a,u64 b){ asm("fma.rn.f32x2 %0, %1, %2, %0;":"+l"(d):"l"(a),"l"(b)); }
__device__ __forceinline__ float2 upk2(u64 v){ float lo,hi; asm("mov.b64 {%0, %1}, %2;":"=f"(lo),"=f"(hi):"l"(v)); return make_float2(lo,hi); }
__device__ __forceinline__ void mma16816(float* d, const uint32_t* a, const uint32_t* b){
    asm volatile("mma.sync.aligned.m16n8k16.row.col.f32.bf16.bf16.f32 "
        "{%0,%1,%2,%3}, {%4,%5,%6,%7}, {%8,%9}, {%0,%1,%2,%3};"
        : "+f"(d[0]),"+f"(d[1]),"+f"(d[2]),"+f"(d[3])
        : "r"(a[0]),"r"(a[1]),"r"(a[2]),"r"(a[3]),"r"(b[0]),"r"(b[1]));
}
__device__ __forceinline__ void bar_rel(unsigned* p){ asm volatile("red.release.gpu.global.add.u32 [%0], 1;"::"l"(p):"memory"); }
__device__ __forceinline__ unsigned bar_acq(unsigned* p){ unsigned v; asm volatile("ld.acquire.gpu.global.u32 %0, [%1];":"=r"(v):"l"(p):"memory"); return v; }

// ---------- xg GEMM (f32x2, validated): C = A*B^T + b1 + b2 ----------
__global__ void __launch_bounds__(256) gemm_abT(float* __restrict__ C, const float* __restrict__ A,
    const float* __restrict__ Bm, const float* __restrict__ b1, const float* __restrict__ b2,
    int M, int N, int K)
{
    __shared__ __align__(16) float As[8*136], Bs[8*136];
    int tid=threadIdx.x, bm=blockIdx.y, bn=blockIdx.x, tx=tid&15, ty=tid>>4;
    u64 acc[4][4];
#pragma unroll
    for(int i=0;i<4;i++)
#pragma unroll
        for(int j=0;j<4;j++) acc[i][j]=0ull;
    int r=tid>>2, kq=(tid&3)*4;
    const float* Ag=A+(size_t)(bm*64+r)*K+kq;
    const float* Bg=Bm+(size_t)(bn*64+r)*K+kq;
    for(int kt=0;kt<K;kt+=16){
        float4 av=*(const float4*)(Ag+kt), bv=*(const float4*)(Bg+kt);
        __syncthreads();
        int s0=(kq>>1)*136+r*2;
        *(float2*)(As+s0)=make_float2(av.x,av.y); *(float2*)(As+s0+136)=make_float2(av.z,av.w);
        *(float2*)(Bs+s0)=make_float2(bv.x,bv.y); *(float2*)(Bs+s0+136)=make_float2(bv.z,bv.w);
        __syncthreads();
#pragma unroll
        for(int kk=0;kk<8;kk++){
            const ulonglong2* ap=(const ulonglong2*)(As+kk*136+ty*8);
            const ulonglong2* bp=(const ulonglong2*)(Bs+kk*136+tx*8);
            ulonglong2 a01=ap[0],a23=ap[1],b01=bp[0],b23=bp[1];
            u64 af[4]={a01.x,a01.y,a23.x,a23.y}, bf[4]={b01.x,b01.y,b23.x,b23.y};
#pragma unroll
            for(int i=0;i<4;i++)
#pragma unroll
                for(int j=0;j<4;j++) fma2(acc[i][j],af[i],bf[j]);
        }
    }
#pragma unroll
    for(int i=0;i<4;i++){
        int row=bm*64+ty*4+i; float4 o; float* ov=&o.x;
#pragma unroll
        for(int j=0;j<4;j++){ int cn=bn*64+tx*4+j; float2 s=upk2(acc[i][j]); ov[j]=s.x+s.y+b1[cn]+b2[cn]; }
        *(float4*)(C+(size_t)row*N+bn*64+tx*4)=o;
    }
}

// ---------- persistent mma.sync LSTM recurrence ----------
// 64 CTAs x 256 thr. CTA owns cols [8c,8c+8) -> 32 gate-rows (n=4j+g).
// D[m=64 batch, n=32 gate] = Ahi*Whi + Ahi*Wlo + Alo*Whi (K'=1536).
// 8 warps: (m-half) x (k-quarter). D stored [batch][gate] (R9-proven orientation).
__global__ void __launch_bounds__(256,1) lstm_rec_mma(
    const float* __restrict__ Whh, const float* __restrict__ xg,
    float* __restrict__ hseq, float* __restrict__ hlast)
{
    extern __shared__ char sm[];
    int tid=threadIdx.x, wid=tid>>5, lane=tid&31;
    int gid=lane>>2, tig=lane&3;
    int col0=blockIdx.x*8;

    // stage W hi/lo -> [n][k] rows 1024B, 16B-chunk XOR swizzle by n&7
    for(int e=tid;e<32*512;e+=256){
        int n=e>>9, k=e&511;
        float w=Whh[(size_t)((n&3)*HH + col0 + (n>>2))*HH + k];
        __nv_bfloat16 hi=__float2bfloat16(w);
        __nv_bfloat16 lo=__float2bfloat16(w-__bfloat162float(hi));
        int kb=k*2;
        int off=n*1024 + ((((kb>>4)^(n&7)))<<4) + (kb&15);
        *(__nv_bfloat16*)(sm+SWHI+off)=hi;
        *(__nv_bfloat16*)(sm+SWLO+off)=lo;
    }
    int eb=tid>>2, ejp=tid&3;     // epilogue cells: (batch eb, cols 2*ejp, 2*ejp+1)
    float c0=0.f, c1=0.f;
    __syncthreads();

    for(int t=0;t<TT;t++){
        // prefetch this thread's xg gates (independent; hidden behind staging)
        float xv[2][4];
        {
            const float* xq = xg + ((size_t)(eb*TT+t)<<11) + col0 + ejp*2;
#pragma unroll
            for(int g=0;g<4;g++){ xv[0][g]=__ldcs(xq+g*512); xv[1][g]=__ldcs(xq+g*512+1); }
        }
        // stage A = [hhi;hlo] 128x512 bf16 from L2, swizzled
        const uint4* src=(const uint4*)g_hA[t&1];
#pragma unroll 4
        for(int it=0;it<32;it++){
            int idx=tid+it*256;
            int r=idx>>6, kc=idx&63;
            uint4 v=__ldcg(src+idx);
            *(uint4*)(sm+SA+r*1024+((kc^(r&7))<<4))=v;
        }
        __syncthreads();

        {
            int wm=(wid&1)*32;            // m-half (batch rows)
            int k0=(wid>>1)*24;           // k-quarter of 96 k16-blocks
            float d[8][4];
#pragma unroll
            for(int i=0;i<8;i++){ d[i][0]=0.f; d[i][1]=0.f; d[i][2]=0.f; d[i][3]=0.f; }
            int ra[4], rw[4];
#pragma unroll
            for(int i=0;i<4;i++){ ra[i]=(wm+i*8+gid)*1024; rw[i]=(i*8+gid)*1024; }
#pragma unroll 4
            for(int ki=0;ki<24;ki++){
                int kk=k0+ki;
                const char* ab=sm+SA+((kk>=64)?65536:0);           // Ahi / Alo rows
                const char* wb=sm+((kk>=32&&kk<64)?SWLO:SWHI);     // Whi,Wlo,Whi
                int ck=(kk&31)*2;
                int o0=((ck^gid)<<4)+tig*4;
                int o1=(((ck+1)^gid)<<4)+tig*4;
                uint32_t a[2][4], bf[4][2];
#pragma unroll
                for(int mf=0;mf<2;mf++){
                    a[mf][0]=*(const uint32_t*)(ab+ra[mf*2]+o0);
                    a[mf][1]=*(const uint32_t*)(ab+ra[mf*2+1]+o0);
                    a[mf][2]=*(const uint32_t*)(ab+ra[mf*2]+o1);
                    a[mf][3]=*(const uint32_t*)(ab+ra[mf*2+1]+o1);
                }
#pragma unroll
                for(int nf=0;nf<4;nf++){
                    bf[nf][0]=*(const uint32_t*)(wb+rw[nf]+o0);
                    bf[nf][1]=*(const uint32_t*)(wb+rw[nf]+o1);
                }
#pragma unroll
                for(int mf=0;mf<2;mf++)
#pragma unroll
                    for(int nf=0;nf<4;nf++)
                        mma16816(d[mf*4+nf], a[mf], bf[nf]);
            }
            // D store, [batch][gate] (FIX: m=batch major — R9 orientation), buf = k-quarter
            float* db=(float*)(sm+SD0)+(wid>>1)*(64*DSTR);
#pragma unroll
            for(int mf=0;mf<2;mf++)
#pragma unroll
                for(int nf=0;nf<4;nf++){
                    int m0=wm+mf*16+gid, n0=nf*8+tig*2;
                    float* q=d[mf*4+nf];
                    float* p=db+m0*DSTR+n0;      p[0]=q[0]; p[1]=q[1];
                    float* p2=db+(m0+8)*DSTR+n0; p2[0]=q[2]; p2[1]=q[3];
                }
        }
        __syncthreads();

        // epilogue: thread owns cells (eb, 2*ejp+cc); gates at db[eb][4j..4j+3]
        {
            const float* dp=(const float*)(sm+SD0)+eb*DSTR;
            float hv[2];
#pragma unroll
            for(int cc=0;cc<2;cc++){
                int j=ejp*2+cc;
                float gi=0.f,gf=0.f,gg=0.f,go=0.f;
#pragma unroll
                for(int q=0;q<4;q++){
                    const float2* p=(const float2*)(dp+q*(64*DSTR)+4*j);
                    float2 v0=p[0], v1=p[1];
                    gi+=v0.x; gf+=v0.y; gg+=v1.x; go+=v1.y;
                }
                gi+=xv[cc][0]; gf+=xv[cc][1]; gg+=xv[cc][2]; go+=xv[cc][3];
                float& c = cc ? c1 : c0;
                c = sigm(gf)*c + sigm(gi)*tanh_f(gg);
                hv[cc] = sigm(go)*tanh_f(c);
            }
            __nv_bfloat16 h0=__float2bfloat16(hv[0]), h1=__float2bfloat16(hv[1]);
            __nv_bfloat16 l0=__float2bfloat16(hv[0]-__bfloat162float(h0));
            __nv_bfloat16 l1=__float2bfloat16(hv[1]-__bfloat162float(h1));
            uint32_t hp=(uint32_t)__bfloat16_as_ushort(h0)|((uint32_t)__bfloat16_as_ushort(h1)<<16);
            uint32_t lp=(uint32_t)__bfloat16_as_ushort(l0)|((uint32_t)__bfloat16_as_ushort(l1)<<16);
            __nv_bfloat16* dst=g_hA[(t+1)&1];
            int cbase=col0+ejp*2;
            *(uint32_t*)(dst+(size_t)eb*HH+cbase)=hp;
            *(uint32_t*)(dst+(size_t)(64+eb)*HH+cbase)=lp;
            if(hseq) *(float2*)(hseq+((size_t)eb*TT+t)*HH+cbase)=make_float2(hv[0],hv[1]);
            if(hlast && t==TT-1) *(float2*)(hlast+(size_t)eb*HH+cbase)=make_float2(hv[0],hv[1]);
        }

        // grid barrier
        __threadfence();
        __syncthreads();
        if(tid==0){
            bar_rel(&g_bar);
            unsigned target=(unsigned)gridDim.x*(unsigned)(t+1);
            while(bar_acq(&g_bar)<target){}
        }
        __syncthreads();
    }
}

__global__ void init_state(){
    int i=blockIdx.x*blockDim.x+threadIdx.x;
    if(i==0) g_bar=0u;
    if(i<2*128*HH/2) ((uint32_t*)g_hA)[i]=0u;
}

__global__ void out_gemm(float* __restrict__ out, const float* __restrict__ hl,
                         const float* __restrict__ Wo, const float* __restrict__ bo)
{
    int i=blockIdx.x*blockDim.x+threadIdx.x;
    if(i>=BB*DOUT) return;
    int b=i>>5, n=i&31;
    const float4* hp=(const float4*)(hl+b*HH);
    const float4* wp=(const float4*)(Wo+n*HH);
    float s=0.0f;
#pragma unroll 8
    for(int k=0;k<HH/4;k++){ float4 hv=hp[k],wv=wp[k]; s+=hv.x*wv.x+hv.y*wv.y+hv.z*wv.z+hv.w*wv.w; }
    out[i]=s+bo[n];
}

extern "C" void kernel_launch(void* const* d_in, const int* in_sizes, int n_in,
                              void* d_out, int out_size)
{
    const float* x   =(const float*)d_in[0];
    const float* Wih0=(const float*)d_in[1];
    const float* Whh0=(const float*)d_in[2];
    const float* bih0=(const float*)d_in[3];
    const float* bhh0=(const float*)d_in[4];
    const float* Wih1=(const float*)d_in[5];
    const float* Whh1=(const float*)d_in[6];
    const float* bih1=(const float*)d_in[7];
    const float* bhh1=(const float*)d_in[8];
    const float* Wout=(const float*)d_in[9];
    const float* bout=(const float*)d_in[10];
    float* out=(float*)d_out;

    cudaFuncSetAttribute(lstm_rec_mma, cudaFuncAttributeMaxDynamicSharedMemorySize, SMEM_REC);

    void *pxg,*ph1,*phl;
    cudaGetSymbolAddress(&pxg,g_xg);
    cudaGetSymbolAddress(&ph1,g_h1);
    cudaGetSymbolAddress(&phl,g_hlast);
    float* xg=(float*)pxg; float* h1=(float*)ph1; float* hl=(float*)phl;

    dim3 gg(G4/64,(BB*TT)/64);

    init_state<<<256,256>>>();
    gemm_abT<<<gg,256>>>(xg,x,Wih0,bih0,bhh0,BB*TT,G4,64);
    lstm_rec_mma<<<64,256,SMEM_REC>>>(Whh0,xg,h1,nullptr);

    init_state<<<256,256>>>();
    gemm_abT<<<gg,256>>>(xg,h1,Wih1,bih1,bhh1,BB*TT,G4,HH);
    lstm_rec_mma<<<64,256,SMEM_REC>>>(Whh1,xg,nullptr,hl);

    out_gemm<<<(BB*DOUT+127)/128,128>>>(out,hl,Wout,bout);
}

// round 14
// speedup vs baseline: 1.7813x; 1.3972x over previous
#include <cuda_runtime.h>
#include <cuda_bf16.h>
#include <math.h>
#include <stdint.h>

#define BB 64
#define TT 512
#define HH 512
#define G4 2048
#define DOUT 32

typedef unsigned long long u64;

__device__ __align__(256) float g_xg[BB*TT*G4];
__device__ __align__(256) float g_h1[BB*TT*HH];
__device__ __align__(256) __nv_bfloat16 g_hA[2][128*HH];  // rows 0-63 hi, 64-127 lo
__device__ __align__(256) float g_hlast[BB*HH];
__device__ unsigned g_bar;

// ---- recurrence smem (128 CTAs, 4 cols/CTA, 16 gate rows) ----
#define SA    0                       // A: 128 rows x 1024B swizzled
#define SWHI  131072                  // Whi: 16 rows x 1024B
#define SWLO  147456                  // Wlo: 16 rows x 1024B
#define SD0   163840                  // 4 D bufs [m=64][n=16+4] f32, stride 20
#define DSTR  20
#define DBUF  (64*DSTR)               // floats per buf
#define SMEM_REC (SD0 + 4*DBUF*4)     // 184320

__device__ __forceinline__ float rcpa(float x){ float y; asm("rcp.approx.f32 %0, %1;":"=f"(y):"f"(x)); return y; }
__device__ __forceinline__ float sigm(float x){ return rcpa(1.0f+__expf(-x)); }
__device__ __forceinline__ float tanh_f(float x){ return 2.0f*rcpa(1.0f+__expf(-2.0f*x))-1.0f; }
__device__ __forceinline__ void fma2(u64& d,u64 a,u64 b){ asm("fma.rn.f32x2 %0, %1, %2, %0;":"+l"(d):"l"(a),"l"(b)); }
__device__ __forceinline__ float2 upk2(u64 v){ float lo,hi; asm("mov.b64 {%0, %1}, %2;":"=f"(lo),"=f"(hi):"l"(v)); return make_float2(lo,hi); }
__device__ __forceinline__ uint32_t smem_u32(const void* p){
    uint32_t a; asm("{ .reg .u64 t; cvta.to.shared.u64 t, %1; cvt.u32.u64 %0, t; }":"=r"(a):"l"(p)); return a;
}
__device__ __forceinline__ void cpasync16(uint32_t dst, const void* src){
    asm volatile("cp.async.cg.shared.global [%0], [%1], 16;"::"r"(dst),"l"(src):"memory");
}
__device__ __forceinline__ void cpasync_wait(){
    asm volatile("cp.async.commit_group;\ncp.async.wait_group 0;":::"memory");
}
__device__ __forceinline__ void mma16816(float* d, const uint32_t* a, const uint32_t* b){
    asm volatile("mma.sync.aligned.m16n8k16.row.col.f32.bf16.bf16.f32 "
        "{%0,%1,%2,%3}, {%4,%5,%6,%7}, {%8,%9}, {%0,%1,%2,%3};"
        : "+f"(d[0]),"+f"(d[1]),"+f"(d[2]),"+f"(d[3])
        : "r"(a[0]),"r"(a[1]),"r"(a[2]),"r"(a[3]),"r"(b[0]),"r"(b[1]));
}
__device__ __forceinline__ void bar_rel(unsigned* p){ asm volatile("red.release.gpu.global.add.u32 [%0], 1;"::"l"(p):"memory"); }
__device__ __forceinline__ unsigned bar_acq(unsigned* p){ unsigned v; asm volatile("ld.acquire.gpu.global.u32 %0, [%1];":"=r"(v):"l"(p):"memory"); return v; }

// ---------- xg GEMM (f32x2, validated) ----------
__global__ void __launch_bounds__(256) gemm_abT(float* __restrict__ C, const float* __restrict__ A,
    const float* __restrict__ Bm, const float* __restrict__ b1, const float* __restrict__ b2,
    int M, int N, int K)
{
    __shared__ __align__(16) float As[8*136], Bs[8*136];
    int tid=threadIdx.x, bm=blockIdx.y, bn=blockIdx.x, tx=tid&15, ty=tid>>4;
    u64 acc[4][4];
#pragma unroll
    for(int i=0;i<4;i++)
#pragma unroll
        for(int j=0;j<4;j++) acc[i][j]=0ull;
    int r=tid>>2, kq=(tid&3)*4;
    const float* Ag=A+(size_t)(bm*64+r)*K+kq;
    const float* Bg=Bm+(size_t)(bn*64+r)*K+kq;
    for(int kt=0;kt<K;kt+=16){
        float4 av=*(const float4*)(Ag+kt), bv=*(const float4*)(Bg+kt);
        __syncthreads();
        int s0=(kq>>1)*136+r*2;
        *(float2*)(As+s0)=make_float2(av.x,av.y); *(float2*)(As+s0+136)=make_float2(av.z,av.w);
        *(float2*)(Bs+s0)=make_float2(bv.x,bv.y); *(float2*)(Bs+s0+136)=make_float2(bv.z,bv.w);
        __syncthreads();
#pragma unroll
        for(int kk=0;kk<8;kk++){
            const ulonglong2* ap=(const ulonglong2*)(As+kk*136+ty*8);
            const ulonglong2* bp=(const ulonglong2*)(Bs+kk*136+tx*8);
            ulonglong2 a01=ap[0],a23=ap[1],b01=bp[0],b23=bp[1];
            u64 af[4]={a01.x,a01.y,a23.x,a23.y}, bf[4]={b01.x,b01.y,b23.x,b23.y};
#pragma unroll
            for(int i=0;i<4;i++)
#pragma unroll
                for(int j=0;j<4;j++) fma2(acc[i][j],af[i],bf[j]);
        }
    }
#pragma unroll
    for(int i=0;i<4;i++){
        int row=bm*64+ty*4+i; float4 o; float* ov=&o.x;
#pragma unroll
        for(int j=0;j<4;j++){ int cn=bn*64+tx*4+j; float2 s=upk2(acc[i][j]); ov[j]=s.x+s.y+b1[cn]+b2[cn]; }
        *(float4*)(C+(size_t)row*N+bn*64+tx*4)=o;
    }
}

// ---------- persistent mma.sync LSTM recurrence (128 CTAs) ----------
// CTA owns 4 hidden cols -> 16 gate-rows (n=4j+g). D[m=64,n=16], K'=1536 split.
// 8 warps: (m-half) x (k-quarter). Thread epilogue: 1 cell (b=tid&63, j=tid>>6).
__global__ void __launch_bounds__(256,1) lstm_rec_mma(
    const float* __restrict__ Whh, const float* __restrict__ xg,
    float* __restrict__ hseq, float* __restrict__ hlast)
{
    extern __shared__ char sm[];
    uint32_t sbase = smem_u32(sm);
    int tid=threadIdx.x, wid=tid>>5, lane=tid&31;
    int gid=lane>>2, tig=lane&3;
    int col0=blockIdx.x*4;

    // stage W hi/lo: 16 rows x 512 k, 16B-chunk XOR swizzle by n&7
    for(int e=tid;e<16*512;e+=256){
        int n=e>>9, k=e&511;
        float w=Whh[(size_t)((n&3)*HH + col0 + (n>>2))*HH + k];
        __nv_bfloat16 hi=__float2bfloat16(w);
        __nv_bfloat16 lo=__float2bfloat16(w-__bfloat162float(hi));
        int kb=k*2;
        int off=n*1024 + ((((kb>>4)^(n&7)))<<4) + (kb&15);
        *(__nv_bfloat16*)(sm+SWHI+off)=hi;
        *(__nv_bfloat16*)(sm+SWLO+off)=lo;
    }
    int eb=tid&63, ej=tid>>6;     // epilogue cell: (batch eb, col ej)
    float c=0.f;
    __syncthreads();

    for(int t=0;t<TT;t++){
        // xg prefetch: 4 gate values for my cell
        float xv[4];
        {
            const float* xq = xg + ((size_t)(eb*TT+t)<<11) + col0 + ej;
#pragma unroll
            for(int g=0;g<4;g++) xv[g]=__ldcs(xq+g*512);
        }
        // stage A = [hhi;hlo] 128x512 bf16 via cp.async (deep MLP, no reg round-trip)
        {
            const char* src=(const char*)g_hA[t&1];
#pragma unroll
            for(int it=0;it<32;it++){
                int idx=tid+it*256;
                int r=idx>>6, kc=idx&63;
                cpasync16(sbase + SA + r*1024 + ((kc^(r&7))<<4), src + idx*16);
            }
            cpasync_wait();
        }
        __syncthreads();

        {
            int wm=(wid&1)*32;            // m-half (batch rows of [hi;lo])
            int k0=(wid>>1)*24;           // k-quarter of 96 k16-blocks
            float d[4][4];
#pragma unroll
            for(int i=0;i<4;i++){ d[i][0]=0.f; d[i][1]=0.f; d[i][2]=0.f; d[i][3]=0.f; }
            int ra[4], rw[2];
#pragma unroll
            for(int i=0;i<4;i++) ra[i]=(wm+i*8+gid)*1024;
#pragma unroll
            for(int i=0;i<2;i++) rw[i]=(i*8+gid)*1024;
#pragma unroll 4
            for(int ki=0;ki<24;ki++){
                int kk=k0+ki;
                const char* ab=sm+SA+((kk>=64)?65536:0);           // Ahi / Alo rows
                const char* wb=sm+((kk>=32&&kk<64)?SWLO:SWHI);     // Whi,Wlo,Whi
                int ck=(kk&31)*2;
                int o0=((ck^gid)<<4)+tig*4;
                int o1=(((ck+1)^gid)<<4)+tig*4;
                uint32_t a[2][4], bf[2][2];
#pragma unroll
                for(int mf=0;mf<2;mf++){
                    a[mf][0]=*(const uint32_t*)(ab+ra[mf*2]+o0);
                    a[mf][1]=*(const uint32_t*)(ab+ra[mf*2+1]+o0);
                    a[mf][2]=*(const uint32_t*)(ab+ra[mf*2]+o1);
                    a[mf][3]=*(const uint32_t*)(ab+ra[mf*2+1]+o1);
                }
#pragma unroll
                for(int nf=0;nf<2;nf++){
                    bf[nf][0]=*(const uint32_t*)(wb+rw[nf]+o0);
                    bf[nf][1]=*(const uint32_t*)(wb+rw[nf]+o1);
                }
#pragma unroll
                for(int mf=0;mf<2;mf++)
#pragma unroll
                    for(int nf=0;nf<2;nf++)
                        mma16816(d[mf*2+nf], a[mf], bf[nf]);
            }
            // D store [batch][gate] (proven orientation), buf = k-quarter, stride 20
            float* db=(float*)(sm+SD0)+(wid>>1)*DBUF;
#pragma unroll
            for(int mf=0;mf<2;mf++)
#pragma unroll
                for(int nf=0;nf<2;nf++){
                    int m0=wm+mf*16+gid, n0=nf*8+tig*2;
                    float* q=d[mf*2+nf];
                    float* p=db+m0*DSTR+n0;      p[0]=q[0]; p[1]=q[1];
                    float* p2=db+(m0+8)*DSTR+n0; p2[0]=q[2]; p2[1]=q[3];
                }
        }
        __syncthreads();

        // epilogue: cell (eb, ej); gates at db[eb][4*ej .. 4*ej+3], summed over 4 bufs
        {
            const float* dp=(const float*)(sm+SD0)+eb*DSTR+4*ej;
            float4 s0=*(const float4*)(dp);
            float4 s1=*(const float4*)(dp+DBUF);
            float4 s2=*(const float4*)(dp+2*DBUF);
            float4 s3=*(const float4*)(dp+3*DBUF);
            float gi=s0.x+s1.x+s2.x+s3.x+xv[0];
            float gf=s0.y+s1.y+s2.y+s3.y+xv[1];
            float gg=s0.z+s1.z+s2.z+s3.z+xv[2];
            float go=s0.w+s1.w+s2.w+s3.w+xv[3];
            c = sigm(gf)*c + sigm(gi)*tanh_f(gg);
            float hv = sigm(go)*tanh_f(c);

            __nv_bfloat16 h0=__float2bfloat16(hv);
            __nv_bfloat16 l0=__float2bfloat16(hv-__bfloat162float(h0));
            __nv_bfloat16* dst=g_hA[(t+1)&1];
            dst[(size_t)eb*HH+col0+ej]=h0;
            dst[(size_t)(64+eb)*HH+col0+ej]=l0;
            if(hseq) hseq[((size_t)eb*TT+t)*HH+col0+ej]=hv;
            if(hlast && t==TT-1) hlast[(size_t)eb*HH+col0+ej]=hv;
        }

        // grid barrier (release via red; fence dropped — release is cumulative)
        __syncthreads();
        if(tid==0){
            bar_rel(&g_bar);
            unsigned target=(unsigned)gridDim.x*(unsigned)(t+1);
            while(bar_acq(&g_bar)<target){}
        }
        __syncthreads();
    }
}

__global__ void init_state(){
    int i=blockIdx.x*blockDim.x+threadIdx.x;
    if(i==0) g_bar=0u;
    if(i<2*128*HH/2) ((uint32_t*)g_hA)[i]=0u;
}

__global__ void out_gemm(float* __restrict__ out, const float* __restrict__ hl,
                         const float* __restrict__ Wo, const float* __restrict__ bo)
{
    int i=blockIdx.x*blockDim.x+threadIdx.x;
    if(i>=BB*DOUT) return;
    int b=i>>5, n=i&31;
    const float4* hp=(const float4*)(hl+b*HH);
    const float4* wp=(const float4*)(Wo+n*HH);
    float s=0.0f;
#pragma unroll 8
    for(int k=0;k<HH/4;k++){ float4 hv=hp[k],wv=wp[k]; s+=hv.x*wv.x+hv.y*wv.y+hv.z*wv.z+hv.w*wv.w; }
    out[i]=s+bo[n];
}

extern "C" void kernel_launch(void* const* d_in, const int* in_sizes, int n_in,
                              void* d_out, int out_size)
{
    const float* x   =(const float*)d_in[0];
    const float* Wih0=(const float*)d_in[1];
    const float* Whh0=(const float*)d_in[2];
    const float* bih0=(const float*)d_in[3];
    const float* bhh0=(const float*)d_in[4];
    const float* Wih1=(const float*)d_in[5];
    const float* Whh1=(const float*)d_in[6];
    const float* bih1=(const float*)d_in[7];
    const float* bhh1=(const float*)d_in[8];
    const float* Wout=(const float*)d_in[9];
    const float* bout=(const float*)d_in[10];
    float* out=(float*)d_out;

    cudaFuncSetAttribute(lstm_rec_mma, cudaFuncAttributeMaxDynamicSharedMemorySize, SMEM_REC);

    void *pxg,*ph1,*phl;
    cudaGetSymbolAddress(&pxg,g_xg);
    cudaGetSymbolAddress(&ph1,g_h1);
    cudaGetSymbolAddress(&phl,g_hlast);
    float* xg=(float*)pxg; float* h1=(float*)ph1; float* hl=(float*)phl;

    dim3 gg(G4/64,(BB*TT)/64);

    init_state<<<256,256>>>();
    gemm_abT<<<gg,256>>>(xg,x,Wih0,bih0,bhh0,BB*TT,G4,64);
    lstm_rec_mma<<<128,256,SMEM_REC>>>(Whh0,xg,h1,nullptr);

    init_state<<<256,256>>>();
    gemm_abT<<<gg,256>>>(xg,h1,Wih1,bih1,bhh1,BB*TT,G4,HH);
    lstm_rec_mma<<<128,256,SMEM_REC>>>(Whh1,xg,nullptr,hl);

    out_gemm<<<(BB*DOUT+127)/128,128>>>(out,hl,Wout,bout);
}

// round 15
// speedup vs baseline: 2.0643x; 1.1589x over previous
#include <cuda_runtime.h>
#include <cuda_fp16.h>
#include <math.h>
#include <stdint.h>

#define BB 64
#define TT 512
#define HH 512
#define G4 2048
#define DOUT 32

typedef unsigned long long u64;

__device__ __align__(256) float g_xg[BB*TT*G4];
__device__ __align__(256) float g_h1[BB*TT*HH];
__device__ __align__(256) __half g_hA[2][64*HH];   // h as fp16, ping-pong
__device__ __align__(256) float g_hlast[BB*HH];
__device__ unsigned g_bar;

// ---- recurrence smem (128 CTAs, 4 cols/CTA, 16 gate rows) ----
#define SA    0                       // A: 64 rows x 1024B swizzled (fp16 h)
#define SWHI  65536                   // Whi: 16 rows x 1024B
#define SWLO  81920                   // Wlo: 16 rows x 1024B
#define SD0   98304                   // 4 D bufs [m=64][n=16+4] f32, stride 20
#define DSTR  20
#define DBUF  (64*DSTR)
#define SMEM_REC (SD0 + 4*DBUF*4)     // 118784

__device__ __forceinline__ float rcpa(float x){ float y; asm("rcp.approx.f32 %0, %1;":"=f"(y):"f"(x)); return y; }
__device__ __forceinline__ float sigm(float x){ return rcpa(1.0f+__expf(-x)); }
__device__ __forceinline__ float tanh_f(float x){ return 2.0f*rcpa(1.0f+__expf(-2.0f*x))-1.0f; }
__device__ __forceinline__ void fma2(u64& d,u64 a,u64 b){ asm("fma.rn.f32x2 %0, %1, %2, %0;":"+l"(d):"l"(a),"l"(b)); }
__device__ __forceinline__ float2 upk2(u64 v){ float lo,hi; asm("mov.b64 {%0, %1}, %2;":"=f"(lo),"=f"(hi):"l"(v)); return make_float2(lo,hi); }
__device__ __forceinline__ uint32_t smem_u32(const void* p){
    uint32_t a; asm("{ .reg .u64 t; cvta.to.shared.u64 t, %1; cvt.u32.u64 %0, t; }":"=r"(a):"l"(p)); return a;
}
__device__ __forceinline__ void cpasync16(uint32_t dst, const void* src){
    asm volatile("cp.async.cg.shared.global [%0], [%1], 16;"::"r"(dst),"l"(src):"memory");
}
__device__ __forceinline__ void cpasync_wait(){
    asm volatile("cp.async.commit_group;\ncp.async.wait_group 0;":::"memory");
}
__device__ __forceinline__ void mma16816(float* d, const uint32_t* a, const uint32_t* b){
    asm volatile("mma.sync.aligned.m16n8k16.row.col.f32.f16.f16.f32 "
        "{%0,%1,%2,%3}, {%4,%5,%6,%7}, {%8,%9}, {%0,%1,%2,%3};"
        : "+f"(d[0]),"+f"(d[1]),"+f"(d[2]),"+f"(d[3])
        : "r"(a[0]),"r"(a[1]),"r"(a[2]),"r"(a[3]),"r"(b[0]),"r"(b[1]));
}
__device__ __forceinline__ void bar_rel(unsigned* p){ asm volatile("red.release.gpu.global.add.u32 [%0], 1;"::"l"(p):"memory"); }
__device__ __forceinline__ unsigned bar_acq(unsigned* p){ unsigned v; asm volatile("ld.acquire.gpu.global.u32 %0, [%1];":"=r"(v):"l"(p):"memory"); return v; }

// ---------- xg GEMM (f32x2, validated) ----------
__global__ void __launch_bounds__(256) gemm_abT(float* __restrict__ C, const float* __restrict__ A,
    const float* __restrict__ Bm, const float* __restrict__ b1, const float* __restrict__ b2,
    int M, int N, int K)
{
    __shared__ __align__(16) float As[8*136], Bs[8*136];
    int tid=threadIdx.x, bm=blockIdx.y, bn=blockIdx.x, tx=tid&15, ty=tid>>4;
    u64 acc[4][4];
#pragma unroll
    for(int i=0;i<4;i++)
#pragma unroll
        for(int j=0;j<4;j++) acc[i][j]=0ull;
    int r=tid>>2, kq=(tid&3)*4;
    const float* Ag=A+(size_t)(bm*64+r)*K+kq;
    const float* Bg=Bm+(size_t)(bn*64+r)*K+kq;
    for(int kt=0;kt<K;kt+=16){
        float4 av=*(const float4*)(Ag+kt), bv=*(const float4*)(Bg+kt);
        __syncthreads();
        int s0=(kq>>1)*136+r*2;
        *(float2*)(As+s0)=make_float2(av.x,av.y); *(float2*)(As+s0+136)=make_float2(av.z,av.w);
        *(float2*)(Bs+s0)=make_float2(bv.x,bv.y); *(float2*)(Bs+s0+136)=make_float2(bv.z,bv.w);
        __syncthreads();
#pragma unroll
        for(int kk=0;kk<8;kk++){
            const ulonglong2* ap=(const ulonglong2*)(As+kk*136+ty*8);
            const ulonglong2* bp=(const ulonglong2*)(Bs+kk*136+tx*8);
            ulonglong2 a01=ap[0],a23=ap[1],b01=bp[0],b23=bp[1];
            u64 af[4]={a01.x,a01.y,a23.x,a23.y}, bf[4]={b01.x,b01.y,b23.x,b23.y};
#pragma unroll
            for(int i=0;i<4;i++)
#pragma unroll
                for(int j=0;j<4;j++) fma2(acc[i][j],af[i],bf[j]);
        }
    }
#pragma unroll
    for(int i=0;i<4;i++){
        int row=bm*64+ty*4+i; float4 o; float* ov=&o.x;
#pragma unroll
        for(int j=0;j<4;j++){ int cn=bn*64+tx*4+j; float2 s=upk2(acc[i][j]); ov[j]=s.x+s.y+b1[cn]+b2[cn]; }
        *(float4*)(C+(size_t)row*N+bn*64+tx*4)=o;
    }
}

// ---------- persistent mma.sync LSTM recurrence (128 CTAs, fp16 2-term) ----------
// CTA owns 4 hidden cols -> 16 gate-rows (n=4j+g). D[m=64,n=16].
// K'=64 blocks: kk<32 -> A*Whi, kk>=32 -> A*Wlo. 8 warps: m-half x k-quarter(16).
__global__ void __launch_bounds__(256,1) lstm_rec_mma(
    const float* __restrict__ Whh, const float* __restrict__ xg,
    float* __restrict__ hseq, float* __restrict__ hlast)
{
    extern __shared__ char sm[];
    uint32_t sbase = smem_u32(sm);
    int tid=threadIdx.x, wid=tid>>5, lane=tid&31;
    int gid=lane>>2, tig=lane&3;
    int col0=blockIdx.x*4;

    // stage W hi/lo (fp16): 16 rows x 512, 16B-chunk XOR swizzle by n&7
    for(int e=tid;e<16*512;e+=256){
        int n=e>>9, k=e&511;
        float w=Whh[(size_t)((n&3)*HH + col0 + (n>>2))*HH + k];
        __half hi=__float2half(w);
        __half lo=__float2half(w-__half2float(hi));
        int kb=k*2;
        int off=n*1024 + ((((kb>>4)^(n&7)))<<4) + (kb&15);
        *(__half*)(sm+SWHI+off)=hi;
        *(__half*)(sm+SWLO+off)=lo;
    }
    int eb=tid&63, ej=tid>>6;     // epilogue cell: (batch eb, col ej)
    float c=0.f;
    __syncthreads();

    for(int t=0;t<TT;t++){
        // xg prefetch: 4 gate values for my cell
        float xv[4];
        {
            const float* xq = xg + ((size_t)(eb*TT+t)<<11) + col0 + ej;
#pragma unroll
            for(int g=0;g<4;g++) xv[g]=__ldcs(xq+g*512);
        }
        // stage A = h fp16 64x512 via cp.async
        {
            const char* src=(const char*)g_hA[t&1];
#pragma unroll
            for(int it=0;it<16;it++){
                int idx=tid+it*256;
                int r=idx>>6, kc=idx&63;
                cpasync16(sbase + SA + r*1024 + ((kc^(r&7))<<4), src + idx*16);
            }
            cpasync_wait();
        }
        __syncthreads();

        {
            int wm=(wid&1)*32;            // m-half (batch rows)
            int k0=(wid>>1)*16;           // k-quarter of 64 blocks
            float d[4][4];
#pragma unroll
            for(int i=0;i<4;i++){ d[i][0]=0.f; d[i][1]=0.f; d[i][2]=0.f; d[i][3]=0.f; }
            int ra[4], rw[2];
#pragma unroll
            for(int i=0;i<4;i++) ra[i]=(wm+i*8+gid)*1024;
#pragma unroll
            for(int i=0;i<2;i++) rw[i]=(i*8+gid)*1024;
#pragma unroll 4
            for(int ki=0;ki<16;ki++){
                int kk=k0+ki;
                const char* ab=sm+SA;
                const char* wb=sm+((kk>=32)?SWLO:SWHI);
                int ck=(kk&31)*2;
                int o0=((ck^gid)<<4)+tig*4;
                int o1=(((ck+1)^gid)<<4)+tig*4;
                uint32_t a[2][4], bf[2][2];
#pragma unroll
                for(int mf=0;mf<2;mf++){
                    a[mf][0]=*(const uint32_t*)(ab+ra[mf*2]+o0);
                    a[mf][1]=*(const uint32_t*)(ab+ra[mf*2+1]+o0);
                    a[mf][2]=*(const uint32_t*)(ab+ra[mf*2]+o1);
                    a[mf][3]=*(const uint32_t*)(ab+ra[mf*2+1]+o1);
                }
#pragma unroll
                for(int nf=0;nf<2;nf++){
                    bf[nf][0]=*(const uint32_t*)(wb+rw[nf]+o0);
                    bf[nf][1]=*(const uint32_t*)(wb+rw[nf]+o1);
                }
#pragma unroll
                for(int mf=0;mf<2;mf++)
#pragma unroll
                    for(int nf=0;nf<2;nf++)
                        mma16816(d[mf*2+nf], a[mf], bf[nf]);
            }
            // D store [batch][gate], buf = k-quarter, stride 20
            float* db=(float*)(sm+SD0)+(wid>>1)*DBUF;
#pragma unroll
            for(int mf=0;mf<2;mf++)
#pragma unroll
                for(int nf=0;nf<2;nf++){
                    int m0=wm+mf*16+gid, n0=nf*8+tig*2;
                    float* q=d[mf*2+nf];
                    float* p=db+m0*DSTR+n0;      p[0]=q[0]; p[1]=q[1];
                    float* p2=db+(m0+8)*DSTR+n0; p2[0]=q[2]; p2[1]=q[3];
                }
        }
        __syncthreads();

        // epilogue: cell (eb, ej); gates at db[eb][4*ej..4*ej+3], summed over 4 bufs
        {
            const float* dp=(const float*)(sm+SD0)+eb*DSTR+4*ej;
            float4 s0=*(const float4*)(dp);
            float4 s1=*(const float4*)(dp+DBUF);
            float4 s2=*(const float4*)(dp+2*DBUF);
            float4 s3=*(const float4*)(dp+3*DBUF);
            float gi=s0.x+s1.x+s2.x+s3.x+xv[0];
            float gf=s0.y+s1.y+s2.y+s3.y+xv[1];
            float gg=s0.z+s1.z+s2.z+s3.z+xv[2];
            float go=s0.w+s1.w+s2.w+s3.w+xv[3];
            c = sigm(gf)*c + sigm(gi)*tanh_f(gg);
            float hv = sigm(go)*tanh_f(c);

            g_hA[(t+1)&1][(size_t)eb*HH+col0+ej]=__float2half(hv);
            if(hseq) hseq[((size_t)eb*TT+t)*HH+col0+ej]=hv;
            if(hlast && t==TT-1) hlast[(size_t)eb*HH+col0+ej]=hv;
        }

        // grid barrier
        __syncthreads();
        if(tid==0){
            bar_rel(&g_bar);
            unsigned target=(unsigned)gridDim.x*(unsigned)(t+1);
            while(bar_acq(&g_bar)<target){}
        }
        __syncthreads();
    }
}

__global__ void init_state(){
    int i=blockIdx.x*blockDim.x+threadIdx.x;
    if(i==0) g_bar=0u;
    if(i<2*64*HH/2) ((uint32_t*)g_hA)[i]=0u;
}

__global__ void out_gemm(float* __restrict__ out, const float* __restrict__ hl,
                         const float* __restrict__ Wo, const float* __restrict__ bo)
{
    int i=blockIdx.x*blockDim.x+threadIdx.x;
    if(i>=BB*DOUT) return;
    int b=i>>5, n=i&31;
    const float4* hp=(const float4*)(hl+b*HH);
    const float4* wp=(const float4*)(Wo+n*HH);
    float s=0.0f;
#pragma unroll 8
    for(int k=0;k<HH/4;k++){ float4 hv=hp[k],wv=wp[k]; s+=hv.x*wv.x+hv.y*wv.y+hv.z*wv.z+hv.w*wv.w; }
    out[i]=s+bo[n];
}

extern "C" void kernel_launch(void* const* d_in, const int* in_sizes, int n_in,
                              void* d_out, int out_size)
{
    const float* x   =(const float*)d_in[0];
    const float* Wih0=(const float*)d_in[1];
    const float* Whh0=(const float*)d_in[2];
    const float* bih0=(const float*)d_in[3];
    const float* bhh0=(const float*)d_in[4];
    const float* Wih1=(const float*)d_in[5];
    const float* Whh1=(const float*)d_in[6];
    const float* bih1=(const float*)d_in[7];
    const float* bhh1=(const float*)d_in[8];
    const float* Wout=(const float*)d_in[9];
    const float* bout=(const float*)d_in[10];
    float* out=(float*)d_out;

    cudaFuncSetAttribute(lstm_rec_mma, cudaFuncAttributeMaxDynamicSharedMemorySize, SMEM_REC);

    void *pxg,*ph1,*phl;
    cudaGetSymbolAddress(&pxg,g_xg);
    cudaGetSymbolAddress(&ph1,g_h1);
    cudaGetSymbolAddress(&phl,g_hlast);
    float* xg=(float*)pxg; float* h1=(float*)ph1; float* hl=(float*)phl;

    dim3 gg(G4/64,(BB*TT)/64);

    init_state<<<256,256>>>();
    gemm_abT<<<gg,256>>>(xg,x,Wih0,bih0,bhh0,BB*TT,G4,64);
    lstm_rec_mma<<<128,256,SMEM_REC>>>(Whh0,xg,h1,nullptr);

    init_state<<<256,256>>>();
    gemm_abT<<<gg,256>>>(xg,h1,Wih1,bih1,bhh1,BB*TT,G4,HH);
    lstm_rec_mma<<<128,256,SMEM_REC>>>(Whh1,xg,nullptr,hl);

    out_gemm<<<(BB*DOUT+127)/128,128>>>(out,hl,Wout,bout);
}

// round 17
// speedup vs baseline: 2.8056x; 1.3591x over previous
#include <cuda_runtime.h>
#include <cuda_fp16.h>
#include <math.h>
#include <stdint.h>

#define BB 64
#define TT 512
#define HH 512
#define G4 2048
#define DOUT 32

typedef unsigned long long u64;

__device__ __align__(256) float g_xg[BB*TT*G4];
__device__ __align__(256) float g_h1[BB*TT*HH];
__device__ __align__(256) __half g_hA[2][64*HH];   // h as fp16, ping-pong
__device__ __align__(256) float g_hlast[BB*HH];
__device__ unsigned g_bar;

// ---- recurrence smem ----
#define SA    0
#define SWHI  65536
#define SWLO  81920
#define SD0   98304
#define DSTR  20
#define DBUF  (64*DSTR)
#define SMEM_REC (SD0 + 4*DBUF*4)     // 118784

// ---- mma xg-GEMM smem (dynamic): A 16KB + Whi 16KB + Wlo 16KB ----
#define XGA   0
#define XGWH  16384
#define XGWL  32768
#define SMEM_XG 49152

__device__ __forceinline__ float rcpa(float x){ float y; asm("rcp.approx.f32 %0, %1;":"=f"(y):"f"(x)); return y; }
__device__ __forceinline__ float sigm(float x){ return rcpa(1.0f+__expf(-x)); }
__device__ __forceinline__ float tanh_f(float x){ return 2.0f*rcpa(1.0f+__expf(-2.0f*x))-1.0f; }
__device__ __forceinline__ void fma2(u64& d,u64 a,u64 b){ asm("fma.rn.f32x2 %0, %1, %2, %0;":"+l"(d):"l"(a),"l"(b)); }
__device__ __forceinline__ float2 upk2(u64 v){ float lo,hi; asm("mov.b64 {%0, %1}, %2;":"=f"(lo),"=f"(hi):"l"(v)); return make_float2(lo,hi); }
__device__ __forceinline__ uint32_t smem_u32(const void* p){
    uint32_t a; asm("{ .reg .u64 t; cvta.to.shared.u64 t, %1; cvt.u32.u64 %0, t; }":"=r"(a):"l"(p)); return a;
}
__device__ __forceinline__ void cpasync16(uint32_t dst, const void* src){
    asm volatile("cp.async.cg.shared.global [%0], [%1], 16;"::"r"(dst),"l"(src):"memory");
}
__device__ __forceinline__ void cpasync_wait(){
    asm volatile("cp.async.commit_group;\ncp.async.wait_group 0;":::"memory");
}
__device__ __forceinline__ void mma16816(float* d, const uint32_t* a, const uint32_t* b){
    asm volatile("mma.sync.aligned.m16n8k16.row.col.f32.f16.f16.f32 "
        "{%0,%1,%2,%3}, {%4,%5,%6,%7}, {%8,%9}, {%0,%1,%2,%3};"
        : "+f"(d[0]),"+f"(d[1]),"+f"(d[2]),"+f"(d[3])
        : "r"(a[0]),"r"(a[1]),"r"(a[2]),"r"(a[3]),"r"(b[0]),"r"(b[1]));
}
__device__ __forceinline__ void bar_rel(unsigned* p){ asm volatile("red.release.gpu.global.add.u32 [%0], 1;"::"l"(p):"memory"); }
__device__ __forceinline__ unsigned bar_acq(unsigned* p){ unsigned v; asm volatile("ld.acquire.gpu.global.u32 %0, [%1];":"=r"(v):"l"(p):"memory"); return v; }
__device__ __forceinline__ uint32_t h2u(__half2 h){ uint32_t r; memcpy(&r,&h,4); return r; }

// ---------- xg0 GEMM (f32x2, validated; K=64 path) ----------
__global__ void __launch_bounds__(256) gemm_abT(float* __restrict__ C, const float* __restrict__ A,
    const float* __restrict__ Bm, const float* __restrict__ b1, const float* __restrict__ b2,
    int M, int N, int K)
{
    __shared__ __align__(16) float As[8*136], Bs[8*136];
    int tid=threadIdx.x, bm=blockIdx.y, bn=blockIdx.x, tx=tid&15, ty=tid>>4;
    u64 acc[4][4];
#pragma unroll
    for(int i=0;i<4;i++)
#pragma unroll
        for(int j=0;j<4;j++) acc[i][j]=0ull;
    int r=tid>>2, kq=(tid&3)*4;
    const float* Ag=A+(size_t)(bm*64+r)*K+kq;
    const float* Bg=Bm+(size_t)(bn*64+r)*K+kq;
    for(int kt=0;kt<K;kt+=16){
        float4 av=*(const float4*)(Ag+kt), bv=*(const float4*)(Bg+kt);
        __syncthreads();
        int s0=(kq>>1)*136+r*2;
        *(float2*)(As+s0)=make_float2(av.x,av.y); *(float2*)(As+s0+136)=make_float2(av.z,av.w);
        *(float2*)(Bs+s0)=make_float2(bv.x,bv.y); *(float2*)(Bs+s0+136)=make_float2(bv.z,bv.w);
        __syncthreads();
#pragma unroll
        for(int kk=0;kk<8;kk++){
            const ulonglong2* ap=(const ulonglong2*)(As+kk*136+ty*8);
            const ulonglong2* bp=(const ulonglong2*)(Bs+kk*136+tx*8);
            ulonglong2 a01=ap[0],a23=ap[1],b01=bp[0],b23=bp[1];
            u64 af[4]={a01.x,a01.y,a23.x,a23.y}, bf[4]={b01.x,b01.y,b23.x,b23.y};
#pragma unroll
            for(int i=0;i<4;i++)
#pragma unroll
                for(int j=0;j<4;j++) fma2(acc[i][j],af[i],bf[j]);
        }
    }
#pragma unroll
    for(int i=0;i<4;i++){
        int row=bm*64+ty*4+i; float4 o; float* ov=&o.x;
#pragma unroll
        for(int j=0;j<4;j++){ int cn=bn*64+tx*4+j; float2 s=upk2(acc[i][j]); ov[j]=s.x+s.y+b1[cn]+b2[cn]; }
        *(float4*)(C+(size_t)row*N+bn*64+tx*4)=o;
    }
}

// ---------- xg1 GEMM via mma (K=512, fp16 2-term W, fp32->fp16 A) ----------
// C[M,2048] = A[M,512]*W[2048,512]^T + b1 + b2. CTA: m64 x n64, 4 K-chunks of 128.
// Fragment pattern identical to the validated recurrence kernel (256B rows).
__global__ void __launch_bounds__(256) gemm_mma512(float* __restrict__ C,
    const float* __restrict__ A, const float* __restrict__ W,
    const float* __restrict__ b1, const float* __restrict__ b2)
{
    extern __shared__ char sx[];
    int tid=threadIdx.x, wid=tid>>5, lane=tid&31;
    int gid=lane>>2, tig=lane&3;
    int bn=blockIdx.x, bm=blockIdx.y;
    int wm=(wid&1)*32, wn=(wid>>1)*16;

    float dh[2][2][4], dl[2][2][4];
#pragma unroll
    for(int i=0;i<2;i++)
#pragma unroll
        for(int j=0;j<2;j++)
#pragma unroll
            for(int q=0;q<4;q++){ dh[i][j][q]=0.f; dl[i][j][q]=0.f; }

    int ra[4], rw[2];
#pragma unroll
    for(int i=0;i<4;i++) ra[i]=(wm+i*8+gid)*256;
#pragma unroll
    for(int i=0;i<2;i++) rw[i]=(wn+i*8+gid)*256;

    for(int kc=0;kc<4;kc++){
        // stage A chunk: 64 rows x 128 k (fp32 -> fp16), 16B-chunk XOR swizzle
        __syncthreads();
#pragma unroll
        for(int it=0;it<4;it++){
            int g=tid+it*256;             // 0..1023: row=g>>4, grp=g&15 (8 elems)
            int row=g>>4, gp=g&15;
            const float4* s=(const float4*)(A+(size_t)(bm*64+row)*512+kc*128+gp*8);
            float4 v0=s[0], v1=s[1];
            uint4 u;
            u.x=h2u(__floats2half2_rn(v0.x,v0.y)); u.y=h2u(__floats2half2_rn(v0.z,v0.w));
            u.z=h2u(__floats2half2_rn(v1.x,v1.y)); u.w=h2u(__floats2half2_rn(v1.z,v1.w));
            *(uint4*)(sx+XGA+row*256+((gp^(row&7))<<4))=u;
        }
        // stage W chunk hi/lo: rows n (0..63) -> global row bn*64+n
#pragma unroll
        for(int it=0;it<4;it++){
            int g=tid+it*256;
            int row=g>>4, gp=g&15;
            const float4* s=(const float4*)(W+(size_t)(bn*64+row)*512+kc*128+gp*8);
            float4 v0=s[0], v1=s[1];
            float e[8]={v0.x,v0.y,v0.z,v0.w,v1.x,v1.y,v1.z,v1.w};
            __half hi[8]; __half lo[8];
#pragma unroll
            for(int q=0;q<8;q++){ hi[q]=__float2half(e[q]); lo[q]=__float2half(e[q]-__half2float(hi[q])); }
            int off=row*256+((gp^(row&7))<<4);
            *(uint4*)(sx+XGWH+off)=*(uint4*)hi;
            *(uint4*)(sx+XGWL+off)=*(uint4*)lo;
        }
        __syncthreads();

#pragma unroll
        for(int kb=0;kb<8;kb++){
            int o0=(((2*kb)^gid)<<4)+tig*4;
            int o1=(((2*kb+1)^gid)<<4)+tig*4;
            uint32_t a[2][4], bh[2][2], bl[2][2];
#pragma unroll
            for(int mf=0;mf<2;mf++){
                a[mf][0]=*(const uint32_t*)(sx+XGA+ra[mf*2]+o0);
                a[mf][1]=*(const uint32_t*)(sx+XGA+ra[mf*2+1]+o0);
                a[mf][2]=*(const uint32_t*)(sx+XGA+ra[mf*2]+o1);
                a[mf][3]=*(const uint32_t*)(sx+XGA+ra[mf*2+1]+o1);
            }
#pragma unroll
            for(int nf=0;nf<2;nf++){
                bh[nf][0]=*(const uint32_t*)(sx+XGWH+rw[nf]+o0);
                bh[nf][1]=*(const uint32_t*)(sx+XGWH+rw[nf]+o1);
                bl[nf][0]=*(const uint32_t*)(sx+XGWL+rw[nf]+o0);
                bl[nf][1]=*(const uint32_t*)(sx+XGWL+rw[nf]+o1);
            }
#pragma unroll
            for(int mf=0;mf<2;mf++)
#pragma unroll
                for(int nf=0;nf<2;nf++){
                    mma16816(dh[mf][nf], a[mf], bh[nf]);
                    mma16816(dl[mf][nf], a[mf], bl[nf]);
                }
        }
    }

    // epilogue: C[row][col] = dh+dl+bias
#pragma unroll
    for(int nf=0;nf<2;nf++){
        int c0=bn*64+wn+nf*8+tig*2;
        float bia0=b1[c0]+b2[c0], bia1=b1[c0+1]+b2[c0+1];
#pragma unroll
        for(int mf=0;mf<2;mf++){
            int r0=bm*64+wm+mf*16+gid;
            float* q0=dh[mf][nf]; float* q1=dl[mf][nf];
            *(float2*)(C+(size_t)r0*G4+c0)=make_float2(q0[0]+q1[0]+bia0,q0[1]+q1[1]+bia1);
            *(float2*)(C+(size_t)(r0+8)*G4+c0)=make_float2(q0[2]+q1[2]+bia0,q0[3]+q1[3]+bia1);
        }
    }
}

// ---------- persistent mma.sync LSTM recurrence (unchanged from R15) ----------
__global__ void __launch_bounds__(256,1) lstm_rec_mma(
    const float* __restrict__ Whh, const float* __restrict__ xg,
    float* __restrict__ hseq, float* __restrict__ hlast)
{
    extern __shared__ char sm[];
    uint32_t sbase = smem_u32(sm);
    int tid=threadIdx.x, wid=tid>>5, lane=tid&31;
    int gid=lane>>2, tig=lane&3;
    int col0=blockIdx.x*4;

    for(int e=tid;e<16*512;e+=256){
        int n=e>>9, k=e&511;
        float w=Whh[(size_t)((n&3)*HH + col0 + (n>>2))*HH + k];
        __half hi=__float2half(w);
        __half lo=__float2half(w-__half2float(hi));
        int kb=k*2;
        int off=n*1024 + ((((kb>>4)^(n&7)))<<4) + (kb&15);
        *(__half*)(sm+SWHI+off)=hi;
        *(__half*)(sm+SWLO+off)=lo;
    }
    int eb=tid&63, ej=tid>>6;
    float c=0.f;
    __syncthreads();

    for(int t=0;t<TT;t++){
        float xv[4];
        {
            const float* xq = xg + ((size_t)(eb*TT+t)<<11) + col0 + ej;
#pragma unroll
            for(int g=0;g<4;g++) xv[g]=__ldcs(xq+g*512);
        }
        {
            const char* src=(const char*)g_hA[t&1];
#pragma unroll
            for(int it=0;it<16;it++){
                int idx=tid+it*256;
                int r=idx>>6, kc=idx&63;
                cpasync16(sbase + SA + r*1024 + ((kc^(r&7))<<4), src + idx*16);
            }
            cpasync_wait();
        }
        __syncthreads();

        {
            int wm=(wid&1)*32;
            int k0=(wid>>1)*16;
            float d[4][4];
#pragma unroll
            for(int i=0;i<4;i++){ d[i][0]=0.f; d[i][1]=0.f; d[i][2]=0.f; d[i][3]=0.f; }
            int ra[4], rw[2];
#pragma unroll
            for(int i=0;i<4;i++) ra[i]=(wm+i*8+gid)*1024;
#pragma unroll
            for(int i=0;i<2;i++) rw[i]=(i*8+gid)*1024;
#pragma unroll 4
            for(int ki=0;ki<16;ki++){
                int kk=k0+ki;
                const char* ab=sm+SA;
                const char* wb=sm+((kk>=32)?SWLO:SWHI);
                int ck=(kk&31)*2;
                int o0=((ck^gid)<<4)+tig*4;
                int o1=(((ck+1)^gid)<<4)+tig*4;
                uint32_t a[2][4], bf[2][2];
#pragma unroll
                for(int mf=0;mf<2;mf++){
                    a[mf][0]=*(const uint32_t*)(ab+ra[mf*2]+o0);
                    a[mf][1]=*(const uint32_t*)(ab+ra[mf*2+1]+o0);
                    a[mf][2]=*(const uint32_t*)(ab+ra[mf*2]+o1);
                    a[mf][3]=*(const uint32_t*)(ab+ra[mf*2+1]+o1);
                }
#pragma unroll
                for(int nf=0;nf<2;nf++){
                    bf[nf][0]=*(const uint32_t*)(wb+rw[nf]+o0);
                    bf[nf][1]=*(const uint32_t*)(wb+rw[nf]+o1);
                }
#pragma unroll
                for(int mf=0;mf<2;mf++)
#pragma unroll
                    for(int nf=0;nf<2;nf++)
                        mma16816(d[mf*2+nf], a[mf], bf[nf]);
            }
            float* db=(float*)(sm+SD0)+(wid>>1)*DBUF;
#pragma unroll
            for(int mf=0;mf<2;mf++)
#pragma unroll
                for(int nf=0;nf<2;nf++){
                    int m0=wm+mf*16+gid, n0=nf*8+tig*2;
                    float* q=d[mf*2+nf];
                    float* p=db+m0*DSTR+n0;      p[0]=q[0]; p[1]=q[1];
                    float* p2=db+(m0+8)*DSTR+n0; p2[0]=q[2]; p2[1]=q[3];
                }
        }
        __syncthreads();

        {
            const float* dp=(const float*)(sm+SD0)+eb*DSTR+4*ej;
            float4 s0=*(const float4*)(dp);
            float4 s1=*(const float4*)(dp+DBUF);
            float4 s2=*(const float4*)(dp+2*DBUF);
            float4 s3=*(const float4*)(dp+3*DBUF);
            float gi=s0.x+s1.x+s2.x+s3.x+xv[0];
            float gf=s0.y+s1.y+s2.y+s3.y+xv[1];
            float gg=s0.z+s1.z+s2.z+s3.z+xv[2];
            float go=s0.w+s1.w+s2.w+s3.w+xv[3];
            c = sigm(gf)*c + sigm(gi)*tanh_f(gg);
            float hv = sigm(go)*tanh_f(c);

            g_hA[(t+1)&1][(size_t)eb*HH+col0+ej]=__float2half(hv);
            if(hseq) hseq[((size_t)eb*TT+t)*HH+col0+ej]=hv;
            if(hlast && t==TT-1) hlast[(size_t)eb*HH+col0+ej]=hv;
        }

        __syncthreads();
        if(tid==0){
            bar_rel(&g_bar);
            unsigned target=(unsigned)gridDim.x*(unsigned)(t+1);
            while(bar_acq(&g_bar)<target){}
        }
        __syncthreads();
    }
}

__global__ void init_state(){
    int i=blockIdx.x*blockDim.x+threadIdx.x;
    if(i==0) g_bar=0u;
    if(i<2*64*HH/2) ((uint32_t*)g_hA)[i]=0u;
}

__global__ void out_gemm(float* __restrict__ out, const float* __restrict__ hl,
                         const float* __restrict__ Wo, const float* __restrict__ bo)
{
    int i=blockIdx.x*blockDim.x+threadIdx.x;
    if(i>=BB*DOUT) return;
    int b=i>>5, n=i&31;
    const float4* hp=(const float4*)(hl+b*HH);
    const float4* wp=(const float4*)(Wo+n*HH);
    float s=0.0f;
#pragma unroll 8
    for(int k=0;k<HH/4;k++){ float4 hv=hp[k],wv=wp[k]; s+=hv.x*wv.x+hv.y*wv.y+hv.z*wv.z+hv.w*wv.w; }
    out[i]=s+bo[n];
}

extern "C" void kernel_launch(void* const* d_in, const int* in_sizes, int n_in,
                              void* d_out, int out_size)
{
    const float* x   =(const float*)d_in[0];
    const float* Wih0=(const float*)d_in[1];
    const float* Whh0=(const float*)d_in[2];
    const float* bih0=(const float*)d_in[3];
    const float* bhh0=(const float*)d_in[4];
    const float* Wih1=(const float*)d_in[5];
    const float* Whh1=(const float*)d_in[6];
    const float* bih1=(const float*)d_in[7];
    const float* bhh1=(const float*)d_in[8];
    const float* Wout=(const float*)d_in[9];
    const float* bout=(const float*)d_in[10];
    float* out=(float*)d_out;

    cudaFuncSetAttribute(lstm_rec_mma, cudaFuncAttributeMaxDynamicSharedMemorySize, SMEM_REC);
    cudaFuncSetAttribute(gemm_mma512, cudaFuncAttributeMaxDynamicSharedMemorySize, SMEM_XG);

    void *pxg,*ph1,*phl;
    cudaGetSymbolAddress(&pxg,g_xg);
    cudaGetSymbolAddress(&ph1,g_h1);
    cudaGetSymbolAddress(&phl,g_hlast);
    float* xg=(float*)pxg; float* h1=(float*)ph1; float* hl=(float*)phl;

    dim3 gg(G4/64,(BB*TT)/64);

    init_state<<<256,256>>>();
    gemm_abT<<<gg,256>>>(xg,x,Wih0,bih0,bhh0,BB*TT,G4,64);
    lstm_rec_mma<<<128,256,SMEM_REC>>>(Whh0,xg,h1,nullptr);

    init_state<<<256,256>>>();
    gemm_mma512<<<gg,256,SMEM_XG>>>(xg,h1,Wih1,bih1,bhh1);
    lstm_rec_mma<<<128,256,SMEM_REC>>>(Whh1,xg,nullptr,hl);

    out_gemm<<<(BB*DOUT+127)/128,128>>>(out,hl,Wout,bout);
}